// round 1
// baseline (speedup 1.0000x reference)
#include <cuda_runtime.h>
#include <cstdint>

#define N_BUSES 2000
#define HASH_BITS 19
#define HASH_SIZE (1 << HASH_BITS)
#define HASH_MASK (HASH_SIZE - 1)
#define MAX_EDGES 262144
#define MAX_BN    131072
#define MAX_B     64
#define NTHREADS  256

// Static device scratch (zero-initialized at module load; no runtime allocation).
__device__ unsigned long long g_hash[HASH_SIZE];   // (key+1)<<32 | (edge+1); 0 = empty
__device__ int                g_slot[MAX_EDGES];   // slot each edge resolved to
__device__ float2             g_YV[MAX_BN];        // per-bus YV accumulator (complex)
__device__ float2             g_Smean[MAX_B];      // per-batch mean of S (complex)
__device__ float              g_Vmmean[MAX_B];     // per-batch mean of Vm
__device__ double             g_acc[8];            // d1re, d1im, d2, d3, mse

// ---------------------------------------------------------------------------
// K1: (a) per-batch means of S and Vm  (b) zero YV + accumulators  (c) hash insert
// ---------------------------------------------------------------------------
__global__ void k1_setup(const float* __restrict__ x,
                         const int*   __restrict__ ei,
                         int B, int BN, int BE, int E)
{
    const int nbZero = (BN + NTHREADS - 1) / NTHREADS;
    const int bid = blockIdx.x;
    const int tid = threadIdx.x;

    if (bid < B) {
        // --- per-batch mean reduction over N_BUSES entries ---
        float sr = 0.f, si = 0.f, vm = 0.f;
        for (int i = tid; i < N_BUSES; i += NTHREADS) {
            const float* p = x + (size_t)(bid * N_BUSES + i) * 6;
            sr += p[0]; si += p[1]; vm += p[2];
        }
        // warp reduce
        for (int o = 16; o > 0; o >>= 1) {
            sr += __shfl_down_sync(0xffffffffu, sr, o);
            si += __shfl_down_sync(0xffffffffu, si, o);
            vm += __shfl_down_sync(0xffffffffu, vm, o);
        }
        __shared__ float sh[3][NTHREADS / 32];
        const int lane = tid & 31, wid = tid >> 5;
        if (lane == 0) { sh[0][wid] = sr; sh[1][wid] = si; sh[2][wid] = vm; }
        __syncthreads();
        if (wid == 0) {
            sr = (lane < NTHREADS / 32) ? sh[0][lane] : 0.f;
            si = (lane < NTHREADS / 32) ? sh[1][lane] : 0.f;
            vm = (lane < NTHREADS / 32) ? sh[2][lane] : 0.f;
            for (int o = 4; o > 0; o >>= 1) {
                sr += __shfl_down_sync(0xffffffffu, sr, o);
                si += __shfl_down_sync(0xffffffffu, si, o);
                vm += __shfl_down_sync(0xffffffffu, vm, o);
            }
            if (lane == 0) {
                const float inv = 1.0f / (float)N_BUSES;
                g_Smean[bid]  = make_float2(sr * inv, si * inv);
                g_Vmmean[bid] = vm * inv;
            }
        }
        if (bid == 0 && tid < 8) g_acc[tid] = 0.0;
    } else if (bid < B + nbZero) {
        // --- zero YV ---
        const int i = (bid - B) * NTHREADS + tid;
        if (i < BN) g_YV[i] = make_float2(0.f, 0.f);
    } else {
        // --- hash insert: last-write-wins priority = global edge index ---
        const int e = (bid - B - nbZero) * NTHREADS + tid;
        if (e < BE) {
            const int i = ei[e]      % N_BUSES;
            const int j = ei[BE + e] % N_BUSES;
            const int b = e / E;
            const unsigned key  = (unsigned)((b * N_BUSES + i) * N_BUSES + j); // < 2^27
            const unsigned key1 = key + 1u;
            const unsigned long long newval =
                ((unsigned long long)key1 << 32) | (unsigned)(e + 1);
            int slot = (int)((key * 2654435761u) >> (32 - HASH_BITS)) & HASH_MASK;
            for (;;) {
                unsigned long long prev = atomicCAS(&g_hash[slot], 0ULL, newval);
                if (prev == 0ULL) break;                       // inserted fresh
                if ((unsigned)(prev >> 32) == key1) {          // same key: max edge wins
                    atomicMax(&g_hash[slot], newval);
                    break;
                }
                slot = (slot + 1) & HASH_MASK;
            }
            g_slot[e] = slot;
        }
    }
}

// ---------------------------------------------------------------------------
// K2: winning edges scatter adm * V[b,j] into YV[b,i]
// ---------------------------------------------------------------------------
__global__ void k2_accum(const float* __restrict__ edge_attr,
                         const int*   __restrict__ ei,
                         const float* __restrict__ outputs,
                         int BE, int E)
{
    const int e = blockIdx.x * NTHREADS + threadIdx.x;
    if (e >= BE) return;
    const unsigned long long v = g_hash[g_slot[e]];
    if ((unsigned)(v & 0xffffffffu) != (unsigned)(e + 1)) return;  // superseded
    const int i = ei[e]      % N_BUSES;
    const int j = ei[BE + e] % N_BUSES;
    const int b = e / E;
    const float ar = edge_attr[2 * e], ai = edge_attr[2 * e + 1];
    const int jj = b * N_BUSES + j;
    const float vr = outputs[2 * jj], vi = outputs[2 * jj + 1];
    const int ii = b * N_BUSES + i;
    atomicAdd(&g_YV[ii].x, ar * vr - ai * vi);
    atomicAdd(&g_YV[ii].y, ar * vi + ai * vr);
}

// ---------------------------------------------------------------------------
// K3: per-bus physics terms + MSE, f64 block reduction into g_acc
// ---------------------------------------------------------------------------
__global__ void k3_terms(const float* __restrict__ x,
                         const float* __restrict__ outputs,
                         const float* __restrict__ labels,
                         int BN)
{
    const int idx = blockIdx.x * NTHREADS + threadIdx.x;
    double a0 = 0, a1 = 0, a2 = 0, a3 = 0, a4 = 0;

    if (idx < BN) {
        const int b = idx / N_BUSES;
        const float vr = outputs[2 * idx], vi = outputs[2 * idx + 1];
        const float2 yv = g_YV[idx];
        // Spred = V * conj(YV)
        const float sp_re = vr * yv.x + vi * yv.y;
        const float sp_im = vi * yv.x - vr * yv.y;
        const float* p = x + (size_t)idx * 6;
        const float sr = p[0], si = p[1], vm = p[2];
        const float bt0 = p[3], bt1 = p[4], bt2 = p[5];

        float sn;
        if (sr != 0.f || si != 0.f) {
            sn = 1.f / sqrtf(sr * sr + si * si);
        } else {
            const float2 sm = g_Smean[b];
            sn = 1.f / sqrtf(sm.x * sm.x + sm.y * sm.y);
        }
        const float dr = sp_re - sr, di = sp_im - si;
        const float r1r = (dr * dr - di * di) * bt0;   // complex (d)^2 * bt0
        const float r1i = (2.f * dr * di) * bt0;
        const float r2  = dr * dr * bt1;               // real
        a0 = (double)(sn * (r1r + r2));
        a1 = (double)(sn * r1i);

        const float vminv = (vm != 0.f) ? (1.f / vm) : (1.f / g_Vmmean[b]);
        const float vmag  = sqrtf(vr * vr + vi * vi);
        a2 = (double)(fabsf(vmag * (bt1 + bt2) - vm) * vminv);
        a3 = (double)(fabsf(vi * bt2) * vminv);

        const float l0 = labels[2 * idx], l1 = labels[2 * idx + 1];
        const float e0 = vr - l0, e1 = vi - l1;
        a4 = (double)(e0 * e0) + (double)(e1 * e1);
    }

    // block reduce 5 doubles
    for (int o = 16; o > 0; o >>= 1) {
        a0 += __shfl_down_sync(0xffffffffu, a0, o);
        a1 += __shfl_down_sync(0xffffffffu, a1, o);
        a2 += __shfl_down_sync(0xffffffffu, a2, o);
        a3 += __shfl_down_sync(0xffffffffu, a3, o);
        a4 += __shfl_down_sync(0xffffffffu, a4, o);
    }
    __shared__ double sh[5][NTHREADS / 32];
    const int lane = threadIdx.x & 31, wid = threadIdx.x >> 5;
    if (lane == 0) {
        sh[0][wid] = a0; sh[1][wid] = a1; sh[2][wid] = a2;
        sh[3][wid] = a3; sh[4][wid] = a4;
    }
    __syncthreads();
    if (wid == 0) {
        a0 = (lane < NTHREADS / 32) ? sh[0][lane] : 0.0;
        a1 = (lane < NTHREADS / 32) ? sh[1][lane] : 0.0;
        a2 = (lane < NTHREADS / 32) ? sh[2][lane] : 0.0;
        a3 = (lane < NTHREADS / 32) ? sh[3][lane] : 0.0;
        a4 = (lane < NTHREADS / 32) ? sh[4][lane] : 0.0;
        for (int o = 4; o > 0; o >>= 1) {
            a0 += __shfl_down_sync(0xffffffffu, a0, o);
            a1 += __shfl_down_sync(0xffffffffu, a1, o);
            a2 += __shfl_down_sync(0xffffffffu, a2, o);
            a3 += __shfl_down_sync(0xffffffffu, a3, o);
            a4 += __shfl_down_sync(0xffffffffu, a4, o);
        }
        if (lane == 0) {
            atomicAdd(&g_acc[0], a0);
            atomicAdd(&g_acc[1], a1);
            atomicAdd(&g_acc[2], a2);
            atomicAdd(&g_acc[3], a3);
            atomicAdd(&g_acc[4], a4);
        }
    }
}

// ---------------------------------------------------------------------------
// K4: finalize scalars + hash cleanup (so the next graph replay starts clean)
// ---------------------------------------------------------------------------
__global__ void k4_final(float* __restrict__ out, int out_size, int BE, int BN)
{
    const int e = blockIdx.x * NTHREADS + threadIdx.x;
    if (e < BE) g_hash[g_slot[e]] = 0ULL;

    if (blockIdx.x == 0 && threadIdx.x == 0) {
        const double inv = 1.0 / (double)BN;
        const double d1r = g_acc[0] * inv;
        const double d1i = g_acc[1] * inv;
        const double d2  = g_acc[2] * inv;
        const double d3  = g_acc[3] * inv;
        const double mse = g_acc[4] / (double)(2 * BN);
        const double pr = d1r + d2 + d3;   // W1=W2=W3=1
        const double pi = d1i;
        const double lr = mse + 0.1 * pr;  // LMBDA = 0.1
        const double li = 0.1 * pi;
        if (out_size >= 10) {
            // complex64 layout: (loss, physics, d1, d2, d3) interleaved re/im
            out[0] = (float)lr;  out[1] = (float)li;
            out[2] = (float)pr;  out[3] = (float)pi;
            out[4] = (float)d1r; out[5] = (float)d1i;
            out[6] = (float)d2;  out[7] = 0.f;
            out[8] = (float)d3;  out[9] = 0.f;
        } else {
            out[0] = (float)lr;
            if (out_size > 1) out[1] = (float)pr;
            if (out_size > 2) out[2] = (float)d1r;
            if (out_size > 3) out[3] = (float)d2;
            if (out_size > 4) out[4] = (float)d3;
        }
    }
}

// ---------------------------------------------------------------------------
extern "C" void kernel_launch(void* const* d_in, const int* in_sizes, int n_in,
                              void* d_out, int out_size)
{
    const float* x       = (const float*)d_in[0];
    const float* ea      = (const float*)d_in[1];
    const int*   ei      = (const int*)  d_in[2];
    const float* outputs = (const float*)d_in[3];
    const float* labels  = (const float*)d_in[4];

    const int BN = in_sizes[3] / 2;        // B * N_BUSES
    const int B  = BN / N_BUSES;
    const int BE = in_sizes[2] / 2;        // B * E
    const int E  = BE / B;

    const int nbZero = (BN + NTHREADS - 1) / NTHREADS;
    const int nbEdge = (BE + NTHREADS - 1) / NTHREADS;

    k1_setup<<<B + nbZero + nbEdge, NTHREADS>>>(x, ei, B, BN, BE, E);
    k2_accum<<<nbEdge, NTHREADS>>>(ea, ei, outputs, BE, E);
    k3_terms<<<nbZero, NTHREADS>>>(x, outputs, labels, BN);
    k4_final<<<nbEdge, NTHREADS>>>((float*)d_out, out_size, BE, BN);
}